// round 16
// baseline (speedup 1.0000x reference)
#include <cuda_runtime.h>
#include <cuda_fp16.h>
#include <math.h>
#include <stdint.h>

#define BSZ 2
#define SEQ 2048
#define EMB 2048
#define NH  16
#define NKV 4
#define DH  128
#define MTOT (BSZ*SEQ)
#define KVDIM (NKV*DH)
#define LDKV  (2*KVDIM)
#define SCL2 0.12751744f        // (1/sqrt(128))*log2(e)

__device__ __align__(16) __half g_xh  [MTOT*EMB];
__device__ __align__(16) __half g_Wqh [EMB*EMB];
__device__ __align__(16) __half g_Wkvh[LDKV*EMB];
__device__ __align__(16) __half g_Woh [EMB*EMB];
__device__ __align__(16) __half g_Qh  [MTOT*EMB];
__device__ __align__(16) __half g_KVh [MTOT*LDKV];
__device__ __align__(16) __half g_Oh  [MTOT*EMB];

// ---------------- helpers ---------------------------------------------------
__device__ __forceinline__ void mma16(float c[4], uint32_t a0, uint32_t a1,
                                      uint32_t a2, uint32_t a3, uint32_t b0, uint32_t b1) {
    asm volatile("mma.sync.aligned.m16n8k16.row.col.f32.f16.f16.f32 "
                 "{%0,%1,%2,%3}, {%4,%5,%6,%7}, {%8,%9}, {%0,%1,%2,%3};"
                 : "+f"(c[0]), "+f"(c[1]), "+f"(c[2]), "+f"(c[3])
                 : "r"(a0), "r"(a1), "r"(a2), "r"(a3), "r"(b0), "r"(b1));
}
__device__ __forceinline__ void ldsm4(uint32_t& r0, uint32_t& r1, uint32_t& r2,
                                      uint32_t& r3, uint32_t a) {
    asm volatile("ldmatrix.sync.aligned.m8n8.x4.shared.b16 {%0,%1,%2,%3}, [%4];"
                 : "=r"(r0), "=r"(r1), "=r"(r2), "=r"(r3) : "r"(a));
}
__device__ __forceinline__ void ldsm4t(uint32_t& r0, uint32_t& r1, uint32_t& r2,
                                       uint32_t& r3, uint32_t a) {
    asm volatile("ldmatrix.sync.aligned.m8n8.x4.trans.shared.b16 {%0,%1,%2,%3}, [%4];"
                 : "=r"(r0), "=r"(r1), "=r"(r2), "=r"(r3) : "r"(a));
}
__device__ __forceinline__ void cpa16(uint32_t dst, const void* src) {
    asm volatile("cp.async.cg.shared.global [%0], [%1], 16;" :: "r"(dst), "l"(src));
}
#define CP_COMMIT asm volatile("cp.async.commit_group;")
#define CP_WAIT0  asm volatile("cp.async.wait_group 0;")

__device__ __forceinline__ float ex2f(float x) {
    float y; asm("ex2.approx.ftz.f32 %0, %1;" : "=f"(y) : "f"(x)); return y;
}
__device__ __forceinline__ uint32_t pack2(float a, float b) {
    __half2 h = __floats2half2_rn(a, b); return *reinterpret_cast<uint32_t*>(&h);
}
__device__ __forceinline__ void st2(__half* C, size_t off, float a, float b) {
    *(__half2*)(C + off) = __floats2half2_rn(a, b);
}
__device__ __forceinline__ void st2(float* C, size_t off, float a, float b) {
    *(float2*)(C + off) = make_float2(a, b);
}

// ---------------- fused fp32 -> fp16 conversion (one launch) ----------------
#define CVT_BLOCKS 18432
__global__ void f32to16_all(const float* __restrict__ x,  const float* __restrict__ Wq,
                            const float* __restrict__ Wk, const float* __restrict__ Wv,
                            const float* __restrict__ Wo,
                            __half* __restrict__ xh, __half* __restrict__ wqh,
                            __half* __restrict__ wkvh, __half* __restrict__ woh) {
    const int blk = blockIdx.x;
    const float4* in;
    uint2* out;
    int idx;
    if (blk < 8192)        { in = (const float4*)x;  out = (uint2*)xh;  idx = blk * 256 + threadIdx.x; }
    else if (blk < 12288)  { in = (const float4*)Wq; out = (uint2*)wqh; idx = (blk - 8192) * 256 + threadIdx.x; }
    else if (blk < 13312)  { in = (const float4*)Wk; out = (uint2*)wkvh; idx = (blk - 12288) * 256 + threadIdx.x; }
    else if (blk < 14336)  { in = (const float4*)Wv; out = (uint2*)(wkvh + (size_t)KVDIM * EMB); idx = (blk - 13312) * 256 + threadIdx.x; }
    else                   { in = (const float4*)Wo; out = (uint2*)woh; idx = (blk - 14336) * 256 + threadIdx.x; }
    float4 v = in[idx];
    __half2 a = __floats2half2_rn(v.x, v.y);
    __half2 b = __floats2half2_rn(v.z, v.w);
    uint2 u;
    u.x = *reinterpret_cast<uint32_t*>(&a);
    u.y = *reinterpret_cast<uint32_t*>(&b);
    out[idx] = u;
}

// ---------------- FP16 GEMM: 128x128 tile, BK=64, 4 warps, warp tile 64x64 --
// cp.async double buffer (1 group in flight), single sync per iteration.
#define APAD 72
#define GBUFB (128*APAD*2)
#define GSTRIDE (2*GBUFB)
#define GEMM_SMEM (2*GSTRIDE)     // 73728 B

#define GLOAD(K0, BUF) {                                                    \
        uint32_t db = base + (BUF) * GSTRIDE;                               \
        for (int i = 0; i < 8; i++) {                                       \
            int c = tid + 128 * i;                                          \
            int row = c >> 3, kc = (c & 7) * 8;                             \
            uint32_t off = (uint32_t)(row * APAD + kc) * 2;                 \
            cpa16(db + off,          Ap + (size_t)row * EMB + (K0) + kc);   \
            cpa16(db + GBUFB + off,  Wp + (size_t)row * EMB + (K0) + kc);   \
        } }

#define GEMM_MAIN                                                           \
    float acc[4][8][4];                                                     \
    _Pragma("unroll")                                                       \
    for (int mt = 0; mt < 4; mt++)                                          \
        _Pragma("unroll")                                                   \
        for (int nt = 0; nt < 8; nt++)                                      \
            _Pragma("unroll")                                               \
            for (int e = 0; e < 4; e++) acc[mt][nt][e] = 0.f;               \
    GLOAD(0, 0); CP_COMMIT;                                                 \
    const int nk = EMB >> 6;                                                \
    for (int kt = 0; kt < nk; kt++) {                                       \
        const int cur = kt & 1;                                             \
        CP_WAIT0;                                                           \
        __syncthreads();                                                    \
        if (kt + 1 < nk) { GLOAD((kt + 1) * 64, cur ^ 1); CP_COMMIT; }      \
        const uint32_t aB = base + cur * GSTRIDE, wB = aB + GBUFB;          \
        _Pragma("unroll")                                                   \
        for (int ks = 0; ks < 4; ks++) {                                    \
            uint32_t b0r[8], b1r[8];                                        \
            _Pragma("unroll")                                               \
            for (int ntp = 0; ntp < 4; ntp++)                               \
                ldsm4(b0r[2*ntp], b1r[2*ntp], b0r[2*ntp+1], b1r[2*ntp+1],   \
                      wB + rWoff + (uint32_t)((wn * 64 + ntp * 16) * APAD + ks * 16) * 2); \
            _Pragma("unroll")                                               \
            for (int mt = 0; mt < 4; mt++) {                                \
                uint32_t a0, a1, a2, a3;                                    \
                ldsm4(a0, a1, a2, a3,                                       \
                      aB + rAoff + (uint32_t)((wm * 64 + mt * 16) * APAD + ks * 16) * 2); \
                _Pragma("unroll")                                           \
                for (int nt = 0; nt < 8; nt++)                              \
                    mma16(acc[mt][nt], a0, a1, a2, a3, b0r[nt], b1r[nt]);   \
            }                                                               \
        }                                                                   \
    }

// Fused Q+KV projection: cols [0,2048)->Q, [2048,3072)->KV
__global__ __launch_bounds__(128, 2)
void gemm_qkv(const __half* __restrict__ A,
              const __half* __restrict__ Wq, const __half* __restrict__ Wkv,
              __half* __restrict__ Qo, __half* __restrict__ KVo) {
    extern __shared__ __half gsm[];
    const uint32_t base = (uint32_t)__cvta_generic_to_shared(gsm);

    const int tid = threadIdx.x, lane = tid & 31, wrp = tid >> 5;  // 0..3
    const int g = lane >> 2, q = lane & 3;
    const int wm = wrp >> 1, wn = wrp & 1;
    const int bm = blockIdx.y * 128;
    const int bnRaw = blockIdx.x * 128;

    const uint32_t rAoff = (uint32_t)(((((lane >> 3) & 1) * 8 + (lane & 7)) * APAD + (lane >> 4) * 8) * 2);
    const uint32_t rWoff = (uint32_t)((((lane >> 4) * 8 + (lane & 7)) * APAD + ((lane >> 3) & 1) * 8) * 2);

    const __half* Ap = A + (size_t)bm * EMB;
    const __half* Wp;
    __half* Cp;
    int ldc, bn;
    if (bnRaw < EMB) { Wp = Wq + (size_t)bnRaw * EMB;          Cp = Qo;  ldc = EMB;  bn = bnRaw; }
    else             { Wp = Wkv + (size_t)(bnRaw - EMB) * EMB; Cp = KVo; ldc = LDKV; bn = bnRaw - EMB; }

    GEMM_MAIN

#pragma unroll
    for (int mt = 0; mt < 4; mt++) {
        const int row = bm + wm * 64 + mt * 16 + g;
#pragma unroll
        for (int nt = 0; nt < 8; nt++) {
            const int col = bn + wn * 64 + nt * 8 + 2 * q;
            st2(Cp, (size_t)row * ldc + col,       acc[mt][nt][0], acc[mt][nt][1]);
            st2(Cp, (size_t)(row + 8) * ldc + col, acc[mt][nt][2], acc[mt][nt][3]);
        }
    }
}

// O-projection (fp32 out)
__global__ __launch_bounds__(128, 2)
void gemm_out(const __half* __restrict__ A, const __half* __restrict__ W,
              float* __restrict__ C) {
    extern __shared__ __half gsm[];
    const uint32_t base = (uint32_t)__cvta_generic_to_shared(gsm);

    const int tid = threadIdx.x, lane = tid & 31, wrp = tid >> 5;
    const int g = lane >> 2, q = lane & 3;
    const int wm = wrp >> 1, wn = wrp & 1;
    const int bm = blockIdx.y * 128, bn = blockIdx.x * 128;

    const uint32_t rAoff = (uint32_t)(((((lane >> 3) & 1) * 8 + (lane & 7)) * APAD + (lane >> 4) * 8) * 2);
    const uint32_t rWoff = (uint32_t)((((lane >> 4) * 8 + (lane & 7)) * APAD + ((lane >> 3) & 1) * 8) * 2);

    const __half* Ap = A + (size_t)bm * EMB;
    const __half* Wp = W + (size_t)bn * EMB;

    GEMM_MAIN

#pragma unroll
    for (int mt = 0; mt < 4; mt++) {
        const int row = bm + wm * 64 + mt * 16 + g;
#pragma unroll
        for (int nt = 0; nt < 8; nt++) {
            const int col = bn + wn * 64 + nt * 8 + 2 * q;
            st2(C, (size_t)row * EMB + col,       acc[mt][nt][0], acc[mt][nt][1]);
            st2(C, (size_t)(row + 8) * EMB + col, acc[mt][nt][2], acc[mt][nt][3]);
        }
    }
}
#undef GEMM_MAIN
#undef GLOAD

// ---------------- FP16 flash attention (Round-12/15 passing version) --------
#define DPAD 136
#define KVB  (64*DPAD*2)
#define ATTN_SMEM_BYTES (4*KVB)

__global__ __launch_bounds__(128, 2)
void attn16(const __half* __restrict__ Q, const __half* __restrict__ KV,
            __half* __restrict__ O) {
    const int qt = (gridDim.x - 1) - blockIdx.x;
    const int h  = blockIdx.y;
    const int b  = blockIdx.z;
    const int kvh = h >> 2;

    extern __shared__ __half smh[];
    const uint32_t sb = (uint32_t)__cvta_generic_to_shared(smh);

    const int tid = threadIdx.x, lane = tid & 31, w = tid >> 5;
    const int g = lane >> 2, q = lane & 3;
    const int qrow0 = b * SEQ + qt * 64;

    const uint32_t rKoff = (uint32_t)((((lane >> 4) * 8 + (lane & 7)) * DPAD + ((lane >> 3) & 1) * 8) * 2);
    const uint32_t rVoff = (uint32_t)(((((lane >> 3) & 1) * 8 + (lane & 7)) * DPAD + (lane >> 4) * 8) * 2);

    const __half* kbase = KV + (size_t)(b * SEQ) * LDKV + kvh * DH;
    const __half* vbase = kbase + KVDIM;

#define LOADKV(KT, BUF) {                                                   \
        const __half* kp = kbase + (size_t)((KT) * 64) * LDKV;              \
        const __half* vp = vbase + (size_t)((KT) * 64) * LDKV;              \
        uint32_t kd = sb + (BUF) * KVB;                                     \
        uint32_t vd = sb + 2 * KVB + (BUF) * KVB;                           \
        for (int i = 0; i < 8; i++) {                                       \
            int c = tid + 128 * i;                                          \
            int row = c >> 4, col = (c & 15) * 8;                           \
            uint32_t off = (uint32_t)(row * DPAD + col) * 2;                \
            cpa16(kd + off, kp + (size_t)row * LDKV + col);                 \
            cpa16(vd + off, vp + (size_t)row * LDKV + col);                 \
        } }

    const int nkt = qt + 1;
    LOADKV(0, 0); CP_COMMIT;

    uint32_t qa[8][4];
    {
        const __half* qb = Q + (size_t)(qrow0 + w * 16) * EMB + h * DH;
#pragma unroll
        for (int ks = 0; ks < 8; ks++) {
            const int d0 = ks * 16 + 2 * q;
            qa[ks][0] = *(const uint32_t*)(qb + (size_t)g * EMB + d0);
            qa[ks][1] = *(const uint32_t*)(qb + (size_t)(g + 8) * EMB + d0);
            qa[ks][2] = *(const uint32_t*)(qb + (size_t)g * EMB + d0 + 8);
            qa[ks][3] = *(const uint32_t*)(qb + (size_t)(g + 8) * EMB + d0 + 8);
        }
    }

    float o[16][4];
#pragma unroll
    for (int nt = 0; nt < 16; nt++)
#pragma unroll
        for (int e = 0; e < 4; e++) o[nt][e] = 0.f;

    float m0 = -INFINITY, m1 = -INFINITY, l0 = 0.f, l1 = 0.f;
    const int qg0 = qt * 64 + w * 16 + g, qg1 = qg0 + 8;

    for (int kt = 0; kt < nkt; kt++) {
        const int cur = kt & 1;
        CP_WAIT0;
        __syncthreads();
        if (kt + 1 < nkt) { LOADKV(kt + 1, cur ^ 1); CP_COMMIT; }

        float s[8][4];
#pragma unroll
        for (int nt = 0; nt < 8; nt++)
#pragma unroll
            for (int e = 0; e < 4; e++) s[nt][e] = 0.f;

        const uint32_t kB = sb + cur * KVB;
#pragma unroll
        for (int ks = 0; ks < 8; ks++) {
            uint32_t b0r[8], b1r[8];
#pragma unroll
            for (int ntp = 0; ntp < 4; ntp++)
                ldsm4(b0r[2 * ntp], b1r[2 * ntp], b0r[2 * ntp + 1], b1r[2 * ntp + 1],
                      kB + rKoff + (uint32_t)(ntp * 16 * DPAD + ks * 16) * 2);
#pragma unroll
            for (int nt = 0; nt < 8; nt++)
                mma16(s[nt], qa[ks][0], qa[ks][1], qa[ks][2], qa[ks][3], b0r[nt], b1r[nt]);
        }

        if (kt == qt) {
#pragma unroll
            for (int nt = 0; nt < 8; nt++) {
                const int kg = kt * 64 + nt * 8 + 2 * q;
                s[nt][0] = (kg     > qg0) ? -INFINITY : s[nt][0] * SCL2;
                s[nt][1] = (kg + 1 > qg0) ? -INFINITY : s[nt][1] * SCL2;
                s[nt][2] = (kg     > qg1) ? -INFINITY : s[nt][2] * SCL2;
                s[nt][3] = (kg + 1 > qg1) ? -INFINITY : s[nt][3] * SCL2;
            }
        } else {
#pragma unroll
            for (int nt = 0; nt < 8; nt++)
#pragma unroll
                for (int e = 0; e < 4; e++) s[nt][e] *= SCL2;
        }

        float rm0 = -INFINITY, rm1 = -INFINITY;
#pragma unroll
        for (int nt = 0; nt < 8; nt++) {
            rm0 = fmaxf(rm0, fmaxf(s[nt][0], s[nt][1]));
            rm1 = fmaxf(rm1, fmaxf(s[nt][2], s[nt][3]));
        }
        rm0 = fmaxf(rm0, __shfl_xor_sync(0xffffffffu, rm0, 1));
        rm0 = fmaxf(rm0, __shfl_xor_sync(0xffffffffu, rm0, 2));
        rm1 = fmaxf(rm1, __shfl_xor_sync(0xffffffffu, rm1, 1));
        rm1 = fmaxf(rm1, __shfl_xor_sync(0xffffffffu, rm1, 2));

        const float mn0 = fmaxf(m0, rm0), mn1 = fmaxf(m1, rm1);
        const float c0 = ex2f(m0 - mn0), c1 = ex2f(m1 - mn1);
        m0 = mn0; m1 = mn1;

        float rs0 = 0.f, rs1 = 0.f;
#pragma unroll
        for (int nt = 0; nt < 8; nt++) {
            s[nt][0] = ex2f(s[nt][0] - mn0);
            s[nt][1] = ex2f(s[nt][1] - mn0);
            s[nt][2] = ex2f(s[nt][2] - mn1);
            s[nt][3] = ex2f(s[nt][3] - mn1);
            rs0 += s[nt][0] + s[nt][1];
            rs1 += s[nt][2] + s[nt][3];
        }
        rs0 += __shfl_xor_sync(0xffffffffu, rs0, 1);
        rs0 += __shfl_xor_sync(0xffffffffu, rs0, 2);
        rs1 += __shfl_xor_sync(0xffffffffu, rs1, 1);
        rs1 += __shfl_xor_sync(0xffffffffu, rs1, 2);
        l0 = l0 * c0 + rs0;
        l1 = l1 * c1 + rs1;

#pragma unroll
        for (int nt = 0; nt < 16; nt++) {
            o[nt][0] *= c0; o[nt][1] *= c0;
            o[nt][2] *= c1; o[nt][3] *= c1;
        }

        const uint32_t vB = sb + 2 * KVB + cur * KVB;
#pragma unroll
        for (int ks2 = 0; ks2 < 4; ks2++) {
            const uint32_t pa0 = pack2(s[2 * ks2][0],     s[2 * ks2][1]);
            const uint32_t pa1 = pack2(s[2 * ks2][2],     s[2 * ks2][3]);
            const uint32_t pa2 = pack2(s[2 * ks2 + 1][0], s[2 * ks2 + 1][1]);
            const uint32_t pa3 = pack2(s[2 * ks2 + 1][2], s[2 * ks2 + 1][3]);
#pragma unroll
            for (int p4 = 0; p4 < 8; p4++) {
                uint32_t r0, r1, r2, r3;
                ldsm4t(r0, r1, r2, r3,
                       vB + rVoff + (uint32_t)(ks2 * 16 * DPAD + p4 * 16) * 2);
                mma16(o[2 * p4],     pa0, pa1, pa2, pa3, r0, r1);
                mma16(o[2 * p4 + 1], pa0, pa1, pa2, pa3, r2, r3);
            }
        }
    }
#undef LOADKV

    const float inv0 = 1.f / l0, inv1 = 1.f / l1;
    __half* ob = O + (size_t)(qrow0 + w * 16) * EMB + h * DH;
#pragma unroll
    for (int nt = 0; nt < 16; nt++) {
        const int d = nt * 8 + 2 * q;
        *(__half2*)(ob + (size_t)g * EMB + d) =
            __floats2half2_rn(o[nt][0] * inv0, o[nt][1] * inv0);
        *(__half2*)(ob + (size_t)(g + 8) * EMB + d) =
            __floats2half2_rn(o[nt][2] * inv1, o[nt][3] * inv1);
    }
}

// ---------------------------------------------------------------------------
extern "C" void kernel_launch(void* const* d_in, const int* in_sizes, int n_in,
                              void* d_out, int out_size) {
    const float* x  = (const float*)d_in[0];
    const float* Wq = (const float*)d_in[1];
    const float* Wk = (const float*)d_in[2];
    const float* Wv = (const float*)d_in[3];
    const float* Wo = (const float*)d_in[4];
    float* out = (float*)d_out;

    void *xh, *wqh, *wkvh, *woh, *qh, *kvh, *oh;
    cudaGetSymbolAddress(&xh,   g_xh);
    cudaGetSymbolAddress(&wqh,  g_Wqh);
    cudaGetSymbolAddress(&wkvh, g_Wkvh);
    cudaGetSymbolAddress(&woh,  g_Woh);
    cudaGetSymbolAddress(&qh,   g_Qh);
    cudaGetSymbolAddress(&kvh,  g_KVh);
    cudaGetSymbolAddress(&oh,   g_Oh);

    cudaFuncSetAttribute(attn16, cudaFuncAttributeMaxDynamicSharedMemorySize,
                         ATTN_SMEM_BYTES);
    cudaFuncSetAttribute(gemm_qkv, cudaFuncAttributeMaxDynamicSharedMemorySize,
                         GEMM_SMEM);
    cudaFuncSetAttribute(gemm_out, cudaFuncAttributeMaxDynamicSharedMemorySize,
                         GEMM_SMEM);

    f32to16_all<<<CVT_BLOCKS, 256>>>(x, Wq, Wk, Wv, Wo,
                                     (__half*)xh, (__half*)wqh,
                                     (__half*)wkvh, (__half*)woh);

    gemm_qkv<<<dim3((EMB + LDKV) / 128, MTOT / 128), 128, GEMM_SMEM>>>(
        (const __half*)xh, (const __half*)wqh, (const __half*)wkvh,
        (__half*)qh, (__half*)kvh);

    attn16<<<dim3(SEQ / 64, NH, BSZ), 128, ATTN_SMEM_BYTES>>>(
        (const __half*)qh, (const __half*)kvh, (__half*)oh);

    gemm_out<<<dim3(EMB / 128, MTOT / 128), 128, GEMM_SMEM>>>(
        (const __half*)oh, (const __half*)woh, out);
}

// round 17
// speedup vs baseline: 1.0259x; 1.0259x over previous
#include <cuda_runtime.h>
#include <cuda_fp16.h>
#include <math.h>
#include <stdint.h>

#define BSZ 2
#define SEQ 2048
#define EMB 2048
#define NH  16
#define NKV 4
#define DH  128
#define MTOT (BSZ*SEQ)
#define KVDIM (NKV*DH)
#define LDKV  (2*KVDIM)
#define SCL2 0.12751744f        // (1/sqrt(128))*log2(e)

__device__ __align__(16) __half g_xh  [MTOT*EMB];
__device__ __align__(16) __half g_Wqh [EMB*EMB];
__device__ __align__(16) __half g_Wkvh[LDKV*EMB];
__device__ __align__(16) __half g_Woh [EMB*EMB];
__device__ __align__(16) __half g_Qh  [MTOT*EMB];
__device__ __align__(16) __half g_KVh [MTOT*LDKV];
__device__ __align__(16) __half g_Oh  [MTOT*EMB];

// ---------------- helpers ---------------------------------------------------
__device__ __forceinline__ void mma16(float c[4], uint32_t a0, uint32_t a1,
                                      uint32_t a2, uint32_t a3, uint32_t b0, uint32_t b1) {
    asm volatile("mma.sync.aligned.m16n8k16.row.col.f32.f16.f16.f32 "
                 "{%0,%1,%2,%3}, {%4,%5,%6,%7}, {%8,%9}, {%0,%1,%2,%3};"
                 : "+f"(c[0]), "+f"(c[1]), "+f"(c[2]), "+f"(c[3])
                 : "r"(a0), "r"(a1), "r"(a2), "r"(a3), "r"(b0), "r"(b1));
}
__device__ __forceinline__ void ldsm4(uint32_t& r0, uint32_t& r1, uint32_t& r2,
                                      uint32_t& r3, uint32_t a) {
    asm volatile("ldmatrix.sync.aligned.m8n8.x4.shared.b16 {%0,%1,%2,%3}, [%4];"
                 : "=r"(r0), "=r"(r1), "=r"(r2), "=r"(r3) : "r"(a));
}
__device__ __forceinline__ void ldsm4t(uint32_t& r0, uint32_t& r1, uint32_t& r2,
                                       uint32_t& r3, uint32_t a) {
    asm volatile("ldmatrix.sync.aligned.m8n8.x4.trans.shared.b16 {%0,%1,%2,%3}, [%4];"
                 : "=r"(r0), "=r"(r1), "=r"(r2), "=r"(r3) : "r"(a));
}
__device__ __forceinline__ void cpa16(uint32_t dst, const void* src) {
    asm volatile("cp.async.cg.shared.global [%0], [%1], 16;" :: "r"(dst), "l"(src));
}
#define CP_COMMIT asm volatile("cp.async.commit_group;")
#define CP_WAIT0  asm volatile("cp.async.wait_group 0;")

__device__ __forceinline__ float ex2f(float x) {
    float y; asm("ex2.approx.ftz.f32 %0, %1;" : "=f"(y) : "f"(x)); return y;
}
__device__ __forceinline__ uint32_t pack2(float a, float b) {
    __half2 h = __floats2half2_rn(a, b); return *reinterpret_cast<uint32_t*>(&h);
}
__device__ __forceinline__ void st2(__half* C, size_t off, float a, float b) {
    *(__half2*)(C + off) = __floats2half2_rn(a, b);
}
__device__ __forceinline__ void st2(float* C, size_t off, float a, float b) {
    *(float2*)(C + off) = make_float2(a, b);
}

// ---------------- fused fp32 -> fp16 conversion (one launch) ----------------
#define CVT_BLOCKS 18432
__global__ void f32to16_all(const float* __restrict__ x,  const float* __restrict__ Wq,
                            const float* __restrict__ Wk, const float* __restrict__ Wv,
                            const float* __restrict__ Wo,
                            __half* __restrict__ xh, __half* __restrict__ wqh,
                            __half* __restrict__ wkvh, __half* __restrict__ woh) {
    const int blk = blockIdx.x;
    const float4* in;
    uint2* out;
    int idx;
    if (blk < 8192)        { in = (const float4*)x;  out = (uint2*)xh;  idx = blk * 256 + threadIdx.x; }
    else if (blk < 12288)  { in = (const float4*)Wq; out = (uint2*)wqh; idx = (blk - 8192) * 256 + threadIdx.x; }
    else if (blk < 13312)  { in = (const float4*)Wk; out = (uint2*)wkvh; idx = (blk - 12288) * 256 + threadIdx.x; }
    else if (blk < 14336)  { in = (const float4*)Wv; out = (uint2*)(wkvh + (size_t)KVDIM * EMB); idx = (blk - 13312) * 256 + threadIdx.x; }
    else                   { in = (const float4*)Wo; out = (uint2*)woh; idx = (blk - 14336) * 256 + threadIdx.x; }
    float4 v = in[idx];
    __half2 a = __floats2half2_rn(v.x, v.y);
    __half2 b = __floats2half2_rn(v.z, v.w);
    uint2 u;
    u.x = *reinterpret_cast<uint32_t*>(&a);
    u.y = *reinterpret_cast<uint32_t*>(&b);
    out[idx] = u;
}

// ---------------- FP16 GEMM: 128x128 tile, BK=64, 8 warps (2x4), wt 64x32 ---
// cp.async double buffer, single sync/iter, explicit fragment double-buffering
// (step it=ks*4+mt prefetches frags for it+1 into parity-alternating buffers).
#define APAD 72
#define GBUFB (128*APAD*2)
#define GSTRIDE (2*GBUFB)
#define GEMM_SMEM (2*GSTRIDE)     // 73728 B

#define GLOAD(K0, BUF) {                                                    \
        uint32_t db = base + (BUF) * GSTRIDE;                               \
        for (int i = 0; i < 4; i++) {                                       \
            int c = tid + 256 * i;                                          \
            int row = c >> 3, kc = (c & 7) * 8;                             \
            uint32_t off = (uint32_t)(row * APAD + kc) * 2;                 \
            cpa16(db + off,          Ap + (size_t)row * EMB + (K0) + kc);   \
            cpa16(db + GBUFB + off,  Wp + (size_t)row * EMB + (K0) + kc);   \
        } }

#define LDB(P, KS)                                                          \
    ldsm4(bf[P][0], bf[P][1], bf[P][2], bf[P][3],                           \
          wB + rWoff + (uint32_t)((wn * 32) * APAD + (KS) * 16) * 2);       \
    ldsm4(bf[P][4], bf[P][5], bf[P][6], bf[P][7],                           \
          wB + rWoff + (uint32_t)((wn * 32 + 16) * APAD + (KS) * 16) * 2);

#define LDA(P, KS, MT)                                                      \
    ldsm4(af[P][0], af[P][1], af[P][2], af[P][3],                           \
          aB + rAoff + (uint32_t)((wm * 64 + (MT) * 16) * APAD + (KS) * 16) * 2);

#define GEMM_MAIN                                                           \
    float acc[4][4][4];                                                     \
    _Pragma("unroll")                                                       \
    for (int mt = 0; mt < 4; mt++)                                          \
        _Pragma("unroll")                                                   \
        for (int nt = 0; nt < 4; nt++)                                      \
            _Pragma("unroll")                                               \
            for (int e = 0; e < 4; e++) acc[mt][nt][e] = 0.f;               \
    GLOAD(0, 0); CP_COMMIT;                                                 \
    const int nk = EMB >> 6;                                                \
    for (int kt = 0; kt < nk; kt++) {                                       \
        const int cur = kt & 1;                                             \
        CP_WAIT0;                                                           \
        __syncthreads();                                                    \
        if (kt + 1 < nk) { GLOAD((kt + 1) * 64, cur ^ 1); CP_COMMIT; }      \
        const uint32_t aB = base + cur * GSTRIDE, wB = aB + GBUFB;          \
        uint32_t bf[2][8], af[2][4];                                        \
        LDB(0, 0)                                                           \
        LDA(0, 0, 0)                                                        \
        _Pragma("unroll")                                                   \
        for (int it = 0; it < 16; it++) {                                   \
            const int ks = it >> 2, mt = it & 3;                            \
            const int pa = it & 1, pb = ks & 1;                             \
            if (it < 15) {                                                  \
                const int nit = it + 1, nks = nit >> 2, nmt = nit & 3;      \
                if (nmt == 0) { LDB(nks & 1, nks) }                         \
                LDA(nit & 1, nks, nmt)                                      \
            }                                                               \
            _Pragma("unroll")                                               \
            for (int nt = 0; nt < 4; nt++)                                  \
                mma16(acc[mt][nt], af[pa][0], af[pa][1], af[pa][2], af[pa][3], \
                      bf[pb][2 * nt], bf[pb][2 * nt + 1]);                  \
        }                                                                   \
    }

// Fused Q+KV projection: cols [0,2048)->Q, [2048,3072)->KV
__global__ __launch_bounds__(256, 2)
void gemm_qkv(const __half* __restrict__ A,
              const __half* __restrict__ Wq, const __half* __restrict__ Wkv,
              __half* __restrict__ Qo, __half* __restrict__ KVo) {
    extern __shared__ __half gsm[];
    const uint32_t base = (uint32_t)__cvta_generic_to_shared(gsm);

    const int tid = threadIdx.x, lane = tid & 31, wrp = tid >> 5;
    const int g = lane >> 2, q = lane & 3;
    const int wm = wrp >> 2, wn = wrp & 3;
    const int bm = blockIdx.y * 128;
    const int bnRaw = blockIdx.x * 128;

    const uint32_t rAoff = (uint32_t)(((((lane >> 3) & 1) * 8 + (lane & 7)) * APAD + (lane >> 4) * 8) * 2);
    const uint32_t rWoff = (uint32_t)((((lane >> 4) * 8 + (lane & 7)) * APAD + ((lane >> 3) & 1) * 8) * 2);

    const __half* Ap = A + (size_t)bm * EMB;
    const __half* Wp;
    __half* Cp;
    int ldc, bn;
    if (bnRaw < EMB) { Wp = Wq + (size_t)bnRaw * EMB;          Cp = Qo;  ldc = EMB;  bn = bnRaw; }
    else             { Wp = Wkv + (size_t)(bnRaw - EMB) * EMB; Cp = KVo; ldc = LDKV; bn = bnRaw - EMB; }

    GEMM_MAIN

#pragma unroll
    for (int mt = 0; mt < 4; mt++) {
        const int row = bm + wm * 64 + mt * 16 + g;
#pragma unroll
        for (int nt = 0; nt < 4; nt++) {
            const int col = bn + wn * 32 + nt * 8 + 2 * q;
            st2(Cp, (size_t)row * ldc + col,       acc[mt][nt][0], acc[mt][nt][1]);
            st2(Cp, (size_t)(row + 8) * ldc + col, acc[mt][nt][2], acc[mt][nt][3]);
        }
    }
}

// O-projection (fp32 out)
__global__ __launch_bounds__(256, 2)
void gemm_out(const __half* __restrict__ A, const __half* __restrict__ W,
              float* __restrict__ C) {
    extern __shared__ __half gsm[];
    const uint32_t base = (uint32_t)__cvta_generic_to_shared(gsm);

    const int tid = threadIdx.x, lane = tid & 31, wrp = tid >> 5;
    const int g = lane >> 2, q = lane & 3;
    const int wm = wrp >> 2, wn = wrp & 3;
    const int bm = blockIdx.y * 128, bn = blockIdx.x * 128;

    const uint32_t rAoff = (uint32_t)(((((lane >> 3) & 1) * 8 + (lane & 7)) * APAD + (lane >> 4) * 8) * 2);
    const uint32_t rWoff = (uint32_t)((((lane >> 4) * 8 + (lane & 7)) * APAD + ((lane >> 3) & 1) * 8) * 2);

    const __half* Ap = A + (size_t)bm * EMB;
    const __half* Wp = W + (size_t)bn * EMB;

    GEMM_MAIN

#pragma unroll
    for (int mt = 0; mt < 4; mt++) {
        const int row = bm + wm * 64 + mt * 16 + g;
#pragma unroll
        for (int nt = 0; nt < 4; nt++) {
            const int col = bn + wn * 32 + nt * 8 + 2 * q;
            st2(C, (size_t)row * EMB + col,       acc[mt][nt][0], acc[mt][nt][1]);
            st2(C, (size_t)(row + 8) * EMB + col, acc[mt][nt][2], acc[mt][nt][3]);
        }
    }
}
#undef GEMM_MAIN
#undef GLOAD
#undef LDB
#undef LDA

// ---------------- FP16 flash attention (Round-12/15 passing version) --------
#define DPAD 136
#define KVB  (64*DPAD*2)
#define ATTN_SMEM_BYTES (4*KVB)

__global__ __launch_bounds__(128, 2)
void attn16(const __half* __restrict__ Q, const __half* __restrict__ KV,
            __half* __restrict__ O) {
    const int qt = (gridDim.x - 1) - blockIdx.x;
    const int h  = blockIdx.y;
    const int b  = blockIdx.z;
    const int kvh = h >> 2;

    extern __shared__ __half smh[];
    const uint32_t sb = (uint32_t)__cvta_generic_to_shared(smh);

    const int tid = threadIdx.x, lane = tid & 31, w = tid >> 5;
    const int g = lane >> 2, q = lane & 3;
    const int qrow0 = b * SEQ + qt * 64;

    const uint32_t rKoff = (uint32_t)((((lane >> 4) * 8 + (lane & 7)) * DPAD + ((lane >> 3) & 1) * 8) * 2);
    const uint32_t rVoff = (uint32_t)(((((lane >> 3) & 1) * 8 + (lane & 7)) * DPAD + (lane >> 4) * 8) * 2);

    const __half* kbase = KV + (size_t)(b * SEQ) * LDKV + kvh * DH;
    const __half* vbase = kbase + KVDIM;

#define LOADKV(KT, BUF) {                                                   \
        const __half* kp = kbase + (size_t)((KT) * 64) * LDKV;              \
        const __half* vp = vbase + (size_t)((KT) * 64) * LDKV;              \
        uint32_t kd = sb + (BUF) * KVB;                                     \
        uint32_t vd = sb + 2 * KVB + (BUF) * KVB;                           \
        for (int i = 0; i < 8; i++) {                                       \
            int c = tid + 128 * i;                                          \
            int row = c >> 4, col = (c & 15) * 8;                           \
            uint32_t off = (uint32_t)(row * DPAD + col) * 2;                \
            cpa16(kd + off, kp + (size_t)row * LDKV + col);                 \
            cpa16(vd + off, vp + (size_t)row * LDKV + col);                 \
        } }

    const int nkt = qt + 1;
    LOADKV(0, 0); CP_COMMIT;

    uint32_t qa[8][4];
    {
        const __half* qb = Q + (size_t)(qrow0 + w * 16) * EMB + h * DH;
#pragma unroll
        for (int ks = 0; ks < 8; ks++) {
            const int d0 = ks * 16 + 2 * q;
            qa[ks][0] = *(const uint32_t*)(qb + (size_t)g * EMB + d0);
            qa[ks][1] = *(const uint32_t*)(qb + (size_t)(g + 8) * EMB + d0);
            qa[ks][2] = *(const uint32_t*)(qb + (size_t)g * EMB + d0 + 8);
            qa[ks][3] = *(const uint32_t*)(qb + (size_t)(g + 8) * EMB + d0 + 8);
        }
    }

    float o[16][4];
#pragma unroll
    for (int nt = 0; nt < 16; nt++)
#pragma unroll
        for (int e = 0; e < 4; e++) o[nt][e] = 0.f;

    float m0 = -INFINITY, m1 = -INFINITY, l0 = 0.f, l1 = 0.f;
    const int qg0 = qt * 64 + w * 16 + g, qg1 = qg0 + 8;

    for (int kt = 0; kt < nkt; kt++) {
        const int cur = kt & 1;
        CP_WAIT0;
        __syncthreads();
        if (kt + 1 < nkt) { LOADKV(kt + 1, cur ^ 1); CP_COMMIT; }

        float s[8][4];
#pragma unroll
        for (int nt = 0; nt < 8; nt++)
#pragma unroll
            for (int e = 0; e < 4; e++) s[nt][e] = 0.f;

        const uint32_t kB = sb + cur * KVB;
#pragma unroll
        for (int ks = 0; ks < 8; ks++) {
            uint32_t b0r[8], b1r[8];
#pragma unroll
            for (int ntp = 0; ntp < 4; ntp++)
                ldsm4(b0r[2 * ntp], b1r[2 * ntp], b0r[2 * ntp + 1], b1r[2 * ntp + 1],
                      kB + rKoff + (uint32_t)(ntp * 16 * DPAD + ks * 16) * 2);
#pragma unroll
            for (int nt = 0; nt < 8; nt++)
                mma16(s[nt], qa[ks][0], qa[ks][1], qa[ks][2], qa[ks][3], b0r[nt], b1r[nt]);
        }

        if (kt == qt) {
#pragma unroll
            for (int nt = 0; nt < 8; nt++) {
                const int kg = kt * 64 + nt * 8 + 2 * q;
                s[nt][0] = (kg     > qg0) ? -INFINITY : s[nt][0] * SCL2;
                s[nt][1] = (kg + 1 > qg0) ? -INFINITY : s[nt][1] * SCL2;
                s[nt][2] = (kg     > qg1) ? -INFINITY : s[nt][2] * SCL2;
                s[nt][3] = (kg + 1 > qg1) ? -INFINITY : s[nt][3] * SCL2;
            }
        } else {
#pragma unroll
            for (int nt = 0; nt < 8; nt++)
#pragma unroll
                for (int e = 0; e < 4; e++) s[nt][e] *= SCL2;
        }

        float rm0 = -INFINITY, rm1 = -INFINITY;
#pragma unroll
        for (int nt = 0; nt < 8; nt++) {
            rm0 = fmaxf(rm0, fmaxf(s[nt][0], s[nt][1]));
            rm1 = fmaxf(rm1, fmaxf(s[nt][2], s[nt][3]));
        }
        rm0 = fmaxf(rm0, __shfl_xor_sync(0xffffffffu, rm0, 1));
        rm0 = fmaxf(rm0, __shfl_xor_sync(0xffffffffu, rm0, 2));
        rm1 = fmaxf(rm1, __shfl_xor_sync(0xffffffffu, rm1, 1));
        rm1 = fmaxf(rm1, __shfl_xor_sync(0xffffffffu, rm1, 2));

        const float mn0 = fmaxf(m0, rm0), mn1 = fmaxf(m1, rm1);
        const float c0 = ex2f(m0 - mn0), c1 = ex2f(m1 - mn1);
        m0 = mn0; m1 = mn1;

        float rs0 = 0.f, rs1 = 0.f;
#pragma unroll
        for (int nt = 0; nt < 8; nt++) {
            s[nt][0] = ex2f(s[nt][0] - mn0);
            s[nt][1] = ex2f(s[nt][1] - mn0);
            s[nt][2] = ex2f(s[nt][2] - mn1);
            s[nt][3] = ex2f(s[nt][3] - mn1);
            rs0 += s[nt][0] + s[nt][1];
            rs1 += s[nt][2] + s[nt][3];
        }
        rs0 += __shfl_xor_sync(0xffffffffu, rs0, 1);
        rs0 += __shfl_xor_sync(0xffffffffu, rs0, 2);
        rs1 += __shfl_xor_sync(0xffffffffu, rs1, 1);
        rs1 += __shfl_xor_sync(0xffffffffu, rs1, 2);
        l0 = l0 * c0 + rs0;
        l1 = l1 * c1 + rs1;

#pragma unroll
        for (int nt = 0; nt < 16; nt++) {
            o[nt][0] *= c0; o[nt][1] *= c0;
            o[nt][2] *= c1; o[nt][3] *= c1;
        }

        const uint32_t vB = sb + 2 * KVB + cur * KVB;
#pragma unroll
        for (int ks2 = 0; ks2 < 4; ks2++) {
            const uint32_t pa0 = pack2(s[2 * ks2][0],     s[2 * ks2][1]);
            const uint32_t pa1 = pack2(s[2 * ks2][2],     s[2 * ks2][3]);
            const uint32_t pa2 = pack2(s[2 * ks2 + 1][0], s[2 * ks2 + 1][1]);
            const uint32_t pa3 = pack2(s[2 * ks2 + 1][2], s[2 * ks2 + 1][3]);
#pragma unroll
            for (int p4 = 0; p4 < 8; p4++) {
                uint32_t r0, r1, r2, r3;
                ldsm4t(r0, r1, r2, r3,
                       vB + rVoff + (uint32_t)(ks2 * 16 * DPAD + p4 * 16) * 2);
                mma16(o[2 * p4],     pa0, pa1, pa2, pa3, r0, r1);
                mma16(o[2 * p4 + 1], pa0, pa1, pa2, pa3, r2, r3);
            }
        }
    }
#undef LOADKV

    const float inv0 = 1.f / l0, inv1 = 1.f / l1;
    __half* ob = O + (size_t)(qrow0 + w * 16) * EMB + h * DH;
#pragma unroll
    for (int nt = 0; nt < 16; nt++) {
        const int d = nt * 8 + 2 * q;
        *(__half2*)(ob + (size_t)g * EMB + d) =
            __floats2half2_rn(o[nt][0] * inv0, o[nt][1] * inv0);
        *(__half2*)(ob + (size_t)(g + 8) * EMB + d) =
            __floats2half2_rn(o[nt][2] * inv1, o[nt][3] * inv1);
    }
}

// ---------------------------------------------------------------------------
extern "C" void kernel_launch(void* const* d_in, const int* in_sizes, int n_in,
                              void* d_out, int out_size) {
    const float* x  = (const float*)d_in[0];
    const float* Wq = (const float*)d_in[1];
    const float* Wk = (const float*)d_in[2];
    const float* Wv = (const float*)d_in[3];
    const float* Wo = (const float*)d_in[4];
    float* out = (float*)d_out;

    void *xh, *wqh, *wkvh, *woh, *qh, *kvh, *oh;
    cudaGetSymbolAddress(&xh,   g_xh);
    cudaGetSymbolAddress(&wqh,  g_Wqh);
    cudaGetSymbolAddress(&wkvh, g_Wkvh);
    cudaGetSymbolAddress(&woh,  g_Woh);
    cudaGetSymbolAddress(&qh,   g_Qh);
    cudaGetSymbolAddress(&kvh,  g_KVh);
    cudaGetSymbolAddress(&oh,   g_Oh);

    cudaFuncSetAttribute(attn16, cudaFuncAttributeMaxDynamicSharedMemorySize,
                         ATTN_SMEM_BYTES);
    cudaFuncSetAttribute(gemm_qkv, cudaFuncAttributeMaxDynamicSharedMemorySize,
                         GEMM_SMEM);
    cudaFuncSetAttribute(gemm_out, cudaFuncAttributeMaxDynamicSharedMemorySize,
                         GEMM_SMEM);

    f32to16_all<<<CVT_BLOCKS, 256>>>(x, Wq, Wk, Wv, Wo,
                                     (__half*)xh, (__half*)wqh,
                                     (__half*)wkvh, (__half*)woh);

    gemm_qkv<<<dim3((EMB + LDKV) / 128, MTOT / 128), 256, GEMM_SMEM>>>(
        (const __half*)xh, (const __half*)wqh, (const __half*)wkvh,
        (__half*)qh, (__half*)kvh);

    attn16<<<dim3(SEQ / 64, NH, BSZ), 128, ATTN_SMEM_BYTES>>>(
        (const __half*)qh, (const __half*)kvh, (__half*)oh);

    gemm_out<<<dim3(EMB / 128, MTOT / 128), 256, GEMM_SMEM>>>(
        (const __half*)oh, (const __half*)woh, out);
}